// round 2
// baseline (speedup 1.0000x reference)
#include <cuda_runtime.h>

// out[i, c] = max_{k<7} x[hex_idx[i,k], c]  for i < L = out_size / C
// C = 512 floats = 128 float4 per row.
// NOTE: hex_idx is int32 on disk (JAX downgrades int64 without x64 mode).

static constexpr int C4 = 128;   // float4 per row (C = 512)
static constexpr int K  = 7;

__global__ void __launch_bounds__(128, 8)
hex_pool_kernel(const float4* __restrict__ x,
                const int* __restrict__ hex_idx,
                float4* __restrict__ out,
                int L)
{
    int i = blockIdx.x;
    if (i >= L) return;
    int c = threadIdx.x;  // 0..127

    const int* row = hex_idx + (long long)i * K;

    // Load all 7 indices first (uniform across CTA -> broadcast loads).
    int j0 = row[0];
    int j1 = row[1];
    int j2 = row[2];
    int j3 = row[3];
    int j4 = row[4];
    int j5 = row[5];
    int j6 = row[6];

    // 7 independent gathers -> MLP=7 hides L2 latency.
    float4 v0 = x[(long long)j0 * C4 + c];
    float4 v1 = x[(long long)j1 * C4 + c];
    float4 v2 = x[(long long)j2 * C4 + c];
    float4 v3 = x[(long long)j3 * C4 + c];
    float4 v4 = x[(long long)j4 * C4 + c];
    float4 v5 = x[(long long)j5 * C4 + c];
    float4 v6 = x[(long long)j6 * C4 + c];

    float4 m;
    m.x = fmaxf(fmaxf(fmaxf(v0.x, v1.x), fmaxf(v2.x, v3.x)), fmaxf(fmaxf(v4.x, v5.x), v6.x));
    m.y = fmaxf(fmaxf(fmaxf(v0.y, v1.y), fmaxf(v2.y, v3.y)), fmaxf(fmaxf(v4.y, v5.y), v6.y));
    m.z = fmaxf(fmaxf(fmaxf(v0.z, v1.z), fmaxf(v2.z, v3.z)), fmaxf(fmaxf(v4.z, v5.z), v6.z));
    m.w = fmaxf(fmaxf(fmaxf(v0.w, v1.w), fmaxf(v2.w, v3.w)), fmaxf(fmaxf(v4.w, v5.w), v6.w));

    out[(long long)i * C4 + c] = m;
}

extern "C" void kernel_launch(void* const* d_in, const int* in_sizes, int n_in,
                              void* d_out, int out_size)
{
    const float4* x   = (const float4*)d_in[0];  // (N, 512) float32
    const int*    idx = (const int*)d_in[1];     // (N, 7) int32 (see note)
    float4*       out = (float4*)d_out;          // (L, 512) float32

    int L = out_size / 512;   // = (N + 6) / 4 = 10242

    hex_pool_kernel<<<L, 128>>>(x, idx, out, L);
}

// round 4
// speedup vs baseline: 1.1123x; 1.1123x over previous
#include <cuda_runtime.h>

// out[i, c] = max_{k<7} x[hex_idx[i,k], c]  for i < L = out_size / 512
// hex_idx is int32 on disk (JAX downgrades int64 without x64 mode).
//
// sm_103a: .L2::evict_last requires 256-bit loads (.v4.b64). So each thread
// gathers a 32B chunk; 64 threads cover one 2048B row; 128-thread CTA = 2 rows.
// Gathers pinned in L2 (evict_last), output streamed out (st.global.cs).

static constexpr int K = 7;

struct F8 { float f[8]; };

__device__ __forceinline__ F8 ldg_el_256(const void* p) {
    unsigned long long r0, r1, r2, r3;
    asm("ld.global.nc.L2::evict_last.v4.b64 {%0,%1,%2,%3}, [%4];"
        : "=l"(r0), "=l"(r1), "=l"(r2), "=l"(r3)
        : "l"(p));
    F8 v;
    v.f[0] = __uint_as_float((unsigned)(r0 & 0xffffffffu));
    v.f[1] = __uint_as_float((unsigned)(r0 >> 32));
    v.f[2] = __uint_as_float((unsigned)(r1 & 0xffffffffu));
    v.f[3] = __uint_as_float((unsigned)(r1 >> 32));
    v.f[4] = __uint_as_float((unsigned)(r2 & 0xffffffffu));
    v.f[5] = __uint_as_float((unsigned)(r2 >> 32));
    v.f[6] = __uint_as_float((unsigned)(r3 & 0xffffffffu));
    v.f[7] = __uint_as_float((unsigned)(r3 >> 32));
    return v;
}

__device__ __forceinline__ void stg_cs_128(float* p, float a, float b, float c, float d) {
    asm volatile("st.global.cs.v4.f32 [%0], {%1,%2,%3,%4};"
                 :: "l"(p), "f"(a), "f"(b), "f"(c), "f"(d)
                 : "memory");
}

__global__ void __launch_bounds__(128)
hex_pool_kernel(const char* __restrict__ x,      // (N, 2048 bytes) rows
                const int*  __restrict__ hex_idx,
                float*      __restrict__ out,    // (L, 512) floats
                int L)
{
    // 2 rows per CTA: threads 0..63 -> row i0, 64..127 -> row i0+1
    int half = threadIdx.x >> 6;          // 0 or 1
    int c    = threadIdx.x & 63;          // 32B chunk index within row
    int i    = blockIdx.x * 2 + half;
    if (i >= L) return;

    const int* r = hex_idx + (long long)i * K;
    int j[K];
#pragma unroll
    for (int k = 0; k < K; k++) j[k] = __ldg(r + k);

    long long coff = (long long)c * 32;

    // 7 independent 256-bit gathers in flight.
    F8 v[K];
#pragma unroll
    for (int k = 0; k < K; k++)
        v[k] = ldg_el_256(x + (long long)j[k] * 2048 + coff);

    float m[8];
#pragma unroll
    for (int e = 0; e < 8; e++) {
        float t = v[0].f[e];
#pragma unroll
        for (int k = 1; k < K; k++) t = fmaxf(t, v[k].f[e]);
        m[e] = t;
    }

    float* op = out + (long long)i * 512 + c * 8;
    stg_cs_128(op,     m[0], m[1], m[2], m[3]);
    stg_cs_128(op + 4, m[4], m[5], m[6], m[7]);
}

extern "C" void kernel_launch(void* const* d_in, const int* in_sizes, int n_in,
                              void* d_out, int out_size)
{
    const char* x   = (const char*)d_in[0];  // (N, 512) float32 rows
    const int*  idx = (const int*)d_in[1];   // (N, 7) int32
    float*      out = (float*)d_out;         // (L, 512) float32

    int L = out_size / 512;   // 10242
    int grid = (L + 1) / 2;

    hex_pool_kernel<<<grid, 128>>>(x, idx, out, L);
}